// round 1
// baseline (speedup 1.0000x reference)
#include <cuda_runtime.h>

#define N_MAX 100000
#define DD 512
#define HH 32

// ---------------- scratch (static __device__, allocation-free) ----------------
static __device__ float g_wqk[64 * DD];     // [ch][k], ch 0-31 = q, 32-63 = k, scaled by 1/512
static __device__ float g_vt[HH * DD];      // [h][d] = nonneg(v_w[d][h])
static __device__ float g_ego[HH];
static __device__ float g_qemb[N_MAX * HH];
static __device__ float g_kemb[N_MAX * HH];
static __device__ float g_attn[N_MAX * HH];

// ---------------- helpers ----------------
__device__ __forceinline__ float nonneg(float w) {
    // elu(w)+1 : w>0 -> w+1 ; w<=0 -> exp(w)
    return w > 0.f ? w + 1.f : __expf(w);
}

__device__ __forceinline__ unsigned long long pack2(float lo, float hi) {
    unsigned long long r;
    asm("mov.b64 %0, {%1,%2};" : "=l"(r) : "f"(lo), "f"(hi));
    return r;
}
__device__ __forceinline__ void unpack2(unsigned long long v, float& lo, float& hi) {
    asm("mov.b64 {%0,%1}, %2;" : "=f"(lo), "=f"(hi) : "l"(v));
}
__device__ __forceinline__ void fma2(unsigned long long& d, unsigned long long a, unsigned long long b) {
    asm("fma.rn.f32x2 %0, %1, %2, %0;" : "+l"(d) : "l"(a), "l"(b));
}

__device__ __forceinline__ void cp_async16(void* s, const void* g) {
    unsigned ss = (unsigned)__cvta_generic_to_shared(s);
    asm volatile("cp.async.cg.shared.global [%0], [%1], 16;" :: "r"(ss), "l"(g));
}
__device__ __forceinline__ void cp_commit() { asm volatile("cp.async.commit_group;"); }
template <int NN>
__device__ __forceinline__ void cp_wait() { asm volatile("cp.async.wait_group %0;" :: "n"(NN)); }

// ---------------- K0: weight preprocessing ----------------
__global__ void prep_kernel(const float* __restrict__ qw, const float* __restrict__ kw,
                            const float* __restrict__ eg, const float* __restrict__ vw) {
    int i = blockIdx.x * blockDim.x + threadIdx.x;
    if (i < 64 * DD) {
        float w = (i < 32 * DD) ? qw[i] : kw[i - 32 * DD];
        g_wqk[i] = nonneg(w) * (1.f / (float)DD);
    }
    int j = i - 64 * DD;
    if (j >= 0 && j < HH * DD) {
        int h = j / DD, d = j % DD;
        g_vt[j] = nonneg(vw[d * HH + h]);
    }
    int e = i - 64 * DD - HH * DD;
    if (e >= 0 && e < HH) g_ego[e] = nonneg(eg[e]);
}

// ---------------- K1: GEMM1  qk_emb = x @ Wqk^T ----------------
// Persistent CTAs. Per block: W (64x512 f32 = 131KB) resident in smem,
// x streamed in 128-row tiles, k in 8 chunks of 64, double-buffered cp.async.
// Register tile: 4 rows x 8 channels, fma.rn.f32x2 over k-pairs.
#define T1_ROWS 128
#define T1_KC   64

__global__ void __launch_bounds__(256, 1) gemm1_kernel(const float* __restrict__ x, int n) {
    extern __shared__ float smem[];
    float*  w_sh  = smem;                      // 64*512 floats
    float4* xbuf0 = (float4*)(smem + 64 * DD); // 2048 float4 (128 rows x 16 kq)
    float4* xbuf1 = xbuf0 + 2048;

    const int tid  = threadIdx.x;
    const int lane = tid & 31;
    const int warp = tid >> 5;

    for (int i = tid; i < 64 * DD; i += 256) w_sh[i] = g_wqk[i];

    const int ntiles = (n + T1_ROWS - 1) / T1_ROWS;
    for (int tile = blockIdx.x; tile < ntiles; tile += (int)gridDim.x) {
        const int row0 = tile * T1_ROWS;

        unsigned long long acc[4][8];
        #pragma unroll
        for (int r = 0; r < 4; r++)
            #pragma unroll
            for (int ch = 0; ch < 8; ch++) acc[r][ch] = 0ull;

        __syncthreads();  // buffers from previous tile fully consumed

        // prefetch chunk 0
        #pragma unroll
        for (int t = 0; t < 8; t++) {
            int idx = tid + t * 256;
            int row = idx >> 4, kq = idx & 15;
            int gr = row0 + row; if (gr > n - 1) gr = n - 1;
            cp_async16(xbuf0 + row * 16 + (kq ^ (row & 15)),
                       x + (size_t)gr * DD + 0 * T1_KC + kq * 4);
        }
        cp_commit();

        #pragma unroll 1
        for (int c = 0; c < 8; c++) {
            float4* cur = (c & 1) ? xbuf1 : xbuf0;
            float4* nxt = (c & 1) ? xbuf0 : xbuf1;
            if (c + 1 < 8) {
                #pragma unroll
                for (int t = 0; t < 8; t++) {
                    int idx = tid + t * 256;
                    int row = idx >> 4, kq = idx & 15;
                    int gr = row0 + row; if (gr > n - 1) gr = n - 1;
                    cp_async16(nxt + row * 16 + (kq ^ (row & 15)),
                               x + (size_t)gr * DD + (c + 1) * T1_KC + kq * 4);
                }
                cp_commit();
                cp_wait<1>();
            } else {
                cp_wait<0>();
            }
            __syncthreads();

            const float* wb = w_sh + (warp * 8) * DD + c * T1_KC;
            const int swz = lane & 15;
            #pragma unroll
            for (int kq = 0; kq < 16; kq++) {
                ulonglong2 xv[4];
                #pragma unroll
                for (int r = 0; r < 4; r++) {
                    int row = lane + 32 * r;
                    xv[r] = ((const ulonglong2*)cur)[row * 16 + (kq ^ swz)];
                }
                #pragma unroll
                for (int ch = 0; ch < 8; ch++) {
                    ulonglong2 wv = *(const ulonglong2*)(wb + ch * DD + kq * 4);
                    #pragma unroll
                    for (int r = 0; r < 4; r++) {
                        fma2(acc[r][ch], xv[r].x, wv.x);
                        fma2(acc[r][ch], xv[r].y, wv.y);
                    }
                }
            }
            __syncthreads();  // compute done before next loader overwrites 'cur'
        }

        // epilogue: reduce pairs and store
        #pragma unroll
        for (int r = 0; r < 4; r++) {
            int row = row0 + lane + 32 * r;
            if (row < n) {
                float v[8];
                #pragma unroll
                for (int ch = 0; ch < 8; ch++) {
                    float lo, hi; unpack2(acc[r][ch], lo, hi);
                    v[ch] = lo + hi;
                }
                float* dst = (warp < 4) ? (g_qemb + (size_t)row * HH + warp * 8)
                                        : (g_kemb + (size_t)row * HH + (warp - 4) * 8);
                ((float4*)dst)[0] = make_float4(v[0], v[1], v[2], v[3]);
                ((float4*)dst)[1] = make_float4(v[4], v[5], v[6], v[7]);
            }
        }
    }
}

// ---------------- K2: gather + attention normalize ----------------
// dst = repeat(arange(N), K)  =>  sum_local[n] = q_emb[n] * (sum_j k_emb[src[n*K+j]]) / K
// Warp per node, lane = head channel. Rows of k_emb are 128B => fully-used L2 lines.
__global__ void __launch_bounds__(256) attn_kernel(const int* __restrict__ src, int n) {
    const int lane = threadIdx.x & 31;
    const int gw   = (blockIdx.x * blockDim.x + threadIdx.x) >> 5;
    const int nw   = (gridDim.x * blockDim.x) >> 5;
    const float ego = g_ego[lane];
    for (int node = gw; node < n; node += nw) {
        int s = src[(size_t)node * 32 + lane];
        float a0 = 0.f, a1 = 0.f, a2 = 0.f, a3 = 0.f;
        #pragma unroll
        for (int j = 0; j < 32; j += 4) {
            int s0 = __shfl_sync(0xffffffffu, s, j);
            int s1 = __shfl_sync(0xffffffffu, s, j + 1);
            int s2 = __shfl_sync(0xffffffffu, s, j + 2);
            int s3 = __shfl_sync(0xffffffffu, s, j + 3);
            a0 += __ldg((const float*)&g_kemb[(size_t)s0 * HH + lane]);
            a1 += __ldg((const float*)&g_kemb[(size_t)s1 * HH + lane]);
            a2 += __ldg((const float*)&g_kemb[(size_t)s2 * HH + lane]);
            a3 += __ldg((const float*)&g_kemb[(size_t)s3 * HH + lane]);
        }
        float acc = (a0 + a1) + (a2 + a3);
        float q = g_qemb[(size_t)node * HH + lane];
        float sc = ego * q * q + q * acc * (1.f / 32.f);
        float ns = sc;
        #pragma unroll
        for (int o = 16; o; o >>= 1) ns += __shfl_xor_sync(0xffffffffu, ns, o);
        g_attn[(size_t)node * HH + lane] = sc / (ns + 1e-9f);
    }
}

// ---------------- K3: GEMM2  out = attn @ Vt ----------------
// Persistent CTAs. Vt (32x512 f32 = 64KB) resident in smem, 32-node tiles,
// register tile 8 nodes x 8 d-floats per thread, f32x2, coalesced STG.128.
__global__ void __launch_bounds__(256, 1) gemm2_kernel(float* __restrict__ out, int n) {
    extern __shared__ float smem[];
    float* vt_sh = smem;            // 32*512
    float* at_sh = smem + HH * DD;  // 32 nodes x 32 h

    const int tid = threadIdx.x;
    for (int i = tid; i < HH * DD; i += 256) vt_sh[i] = g_vt[i];

    const int dg = tid & 63;   // d group: d = dg*4 and dg*4+256
    const int ng = tid >> 6;   // node group: nodes ng*8 .. ng*8+7

    const int ntiles = (n + 31) / 32;
    for (int tile = blockIdx.x; tile < ntiles; tile += (int)gridDim.x) {
        const int node0 = tile * 32;
        const int nn = (n - node0 < 32) ? (n - node0) : 32;
        __syncthreads();
        for (int i = tid; i < nn * HH; i += 256) at_sh[i] = g_attn[(size_t)node0 * HH + i];
        __syncthreads();

        unsigned long long acc[8][4];
        #pragma unroll
        for (int r = 0; r < 8; r++)
            #pragma unroll
            for (int c = 0; c < 4; c++) acc[r][c] = 0ull;

        #pragma unroll
        for (int h4 = 0; h4 < HH; h4 += 4) {
            ulonglong2 vlo[4], vhi[4];
            #pragma unroll
            for (int i = 0; i < 4; i++) {
                vlo[i] = *(const ulonglong2*)(vt_sh + (h4 + i) * DD + dg * 4);
                vhi[i] = *(const ulonglong2*)(vt_sh + (h4 + i) * DD + 256 + dg * 4);
            }
            #pragma unroll
            for (int r = 0; r < 8; r++) {
                float4 a4 = *(const float4*)(at_sh + (ng * 8 + r) * HH + h4);
                unsigned long long b0 = pack2(a4.x, a4.x);
                unsigned long long b1 = pack2(a4.y, a4.y);
                unsigned long long b2 = pack2(a4.z, a4.z);
                unsigned long long b3 = pack2(a4.w, a4.w);
                fma2(acc[r][0], b0, vlo[0].x); fma2(acc[r][1], b0, vlo[0].y);
                fma2(acc[r][2], b0, vhi[0].x); fma2(acc[r][3], b0, vhi[0].y);
                fma2(acc[r][0], b1, vlo[1].x); fma2(acc[r][1], b1, vlo[1].y);
                fma2(acc[r][2], b1, vhi[1].x); fma2(acc[r][3], b1, vhi[1].y);
                fma2(acc[r][0], b2, vlo[2].x); fma2(acc[r][1], b2, vlo[2].y);
                fma2(acc[r][2], b2, vhi[2].x); fma2(acc[r][3], b2, vhi[2].y);
                fma2(acc[r][0], b3, vlo[3].x); fma2(acc[r][1], b3, vlo[3].y);
                fma2(acc[r][2], b3, vhi[3].x); fma2(acc[r][3], b3, vhi[3].y);
            }
        }

        #pragma unroll
        for (int r = 0; r < 8; r++) {
            int node = node0 + ng * 8 + r;
            if (node < n) {
                ulonglong2 lo, hi;
                lo.x = acc[r][0]; lo.y = acc[r][1];
                hi.x = acc[r][2]; hi.y = acc[r][3];
                *(ulonglong2*)(out + (size_t)node * DD + dg * 4)       = lo;
                *(ulonglong2*)(out + (size_t)node * DD + 256 + dg * 4) = hi;
            }
        }
    }
}

// ---------------- host launcher ----------------
extern "C" void kernel_launch(void* const* d_in, const int* in_sizes, int n_in,
                              void* d_out, int out_size) {
    const int*   adj = (const int*)d_in[0];    // [2, N*K]: row 0 = src
    const float* x   = (const float*)d_in[1];  // [N, 512]
    const float* qw  = (const float*)d_in[2];  // [32, 512]
    const float* kw  = (const float*)d_in[3];  // [32, 512]
    const float* eg  = (const float*)d_in[4];  // [1, 32]
    const float* vw  = (const float*)d_in[5];  // [512, 32]
    float* out = (float*)d_out;

    int n = in_sizes[1] / DD;
    if (n > N_MAX) n = N_MAX;

    int nsm = 148;
    cudaDeviceGetAttribute(&nsm, cudaDevAttrMultiProcessorCount, 0);

    prep_kernel<<<(64 * DD + HH * DD + HH + 255) / 256, 256>>>(qw, kw, eg, vw);

    size_t smem1 = (size_t)(64 * DD) * 4 + 2 * 2048 * sizeof(float4);  // 131072 + 65536
    cudaFuncSetAttribute(gemm1_kernel, cudaFuncAttributeMaxDynamicSharedMemorySize, (int)smem1);
    gemm1_kernel<<<nsm, 256, smem1>>>(x, n);

    attn_kernel<<<1024, 256>>>(adj, n);

    size_t smem2 = (size_t)(HH * DD + 32 * HH) * 4;  // 69632
    cudaFuncSetAttribute(gemm2_kernel, cudaFuncAttributeMaxDynamicSharedMemorySize, (int)smem2);
    gemm2_kernel<<<nsm, 256, smem2>>>(out, n);
}

// round 4
// speedup vs baseline: 1.9233x; 1.9233x over previous
#include <cuda_runtime.h>
#include <cuda_bf16.h>
#include <cstdint>

#define N_MAX 100000
#define DD 512
#define HH 32

// ---------------- scratch (static __device__, allocation-free) ----------------
static __device__ __nv_bfloat16 g_wqk_bf[64 * DD];   // [ch][k] bf16, ch0-31=q, 32-63=k, scaled 1/512
static __device__ __nv_bfloat16 g_v_bf[DD * HH];     // [d][h] = nonneg(v_w[d][h]) bf16
static __device__ float         g_ego[HH];
static __device__ float         g_qemb[N_MAX * HH];  // f32
static __device__ __nv_bfloat16 g_kemb_bf[N_MAX * HH];
static __device__ __nv_bfloat16 g_attn_bf[N_MAX * HH];

// ---------------- helpers ----------------
__device__ __forceinline__ float nonneg(float w) { return w > 0.f ? w + 1.f : __expf(w); }

__device__ __forceinline__ uint32_t s2u(const void* p) {
    return (uint32_t)__cvta_generic_to_shared(p);
}

__device__ __forceinline__ void ldsm4(uint32_t (&r)[4], uint32_t addr) {
    asm volatile("ldmatrix.sync.aligned.m8n8.x4.shared.b16 {%0,%1,%2,%3}, [%4];"
                 : "=r"(r[0]), "=r"(r[1]), "=r"(r[2]), "=r"(r[3]) : "r"(addr));
}

__device__ __forceinline__ void mma16816(float (&d)[4], const uint32_t (&a)[4],
                                         uint32_t b0, uint32_t b1) {
    asm volatile(
        "mma.sync.aligned.m16n8k16.row.col.f32.bf16.bf16.f32 "
        "{%0,%1,%2,%3}, {%4,%5,%6,%7}, {%8,%9}, {%0,%1,%2,%3};"
        : "+f"(d[0]), "+f"(d[1]), "+f"(d[2]), "+f"(d[3])
        : "r"(a[0]), "r"(a[1]), "r"(a[2]), "r"(a[3]), "r"(b0), "r"(b1));
}

__device__ __forceinline__ void cp_async16(void* s, const void* g) {
    asm volatile("cp.async.cg.shared.global [%0], [%1], 16;"
                 :: "r"(s2u(s)), "l"(g));
}
__device__ __forceinline__ void cp_commit() { asm volatile("cp.async.commit_group;"); }
template <int NN>
__device__ __forceinline__ void cp_wait() { asm volatile("cp.async.wait_group %0;" :: "n"(NN)); }

__device__ __forceinline__ uint32_t bf2u(float a, float b) {
    __nv_bfloat162 p = __floats2bfloat162_rn(a, b);
    return *(uint32_t*)&p;
}

// ---------------- K0: weight preprocessing ----------------
__global__ void prep_kernel(const float* __restrict__ qw, const float* __restrict__ kw,
                            const float* __restrict__ eg, const float* __restrict__ vw) {
    int i = blockIdx.x * blockDim.x + threadIdx.x;
    if (i < 64 * DD) {
        float w = (i < 32 * DD) ? qw[i] : kw[i - 32 * DD];
        g_wqk_bf[i] = __float2bfloat16(nonneg(w) * (1.f / (float)DD));
    }
    int j = i - 64 * DD;
    if (j >= 0 && j < DD * HH) g_v_bf[j] = __float2bfloat16(nonneg(vw[j]));
    int e = i - 64 * DD - DD * HH;
    if (e >= 0 && e < HH) g_ego[e] = nonneg(eg[e]);
}

// ---------------- K1: GEMM1  qk_emb = x @ Wqk^T  (mma.sync bf16) ----------------
// Persistent CTAs, 256 thr. W [64ch x 512k] bf16 resident in smem (pitch 1040B).
// Per 128-row tile: 8 chunks of k=64, LDG f32 -> cvt bf16 -> STS (pitch 144B), double-buffered.
// Warp tile: 32 rows x 32 ch (2 m-tiles x 4 n-tiles), k-step 16.
#define G1_APITCH 144
#define G1_WPITCH 1040
#define G1_A0     66560
#define G1_A1     84992
#define G1_SMEM   103424

__global__ void __launch_bounds__(256, 1) gemm1_kernel(const float* __restrict__ x, int n) {
    extern __shared__ __align__(16) char sm[];
    const int tid  = threadIdx.x;
    const int lane = tid & 31;
    const int warp = tid >> 5;

    // one-time: W -> smem [ch][k], pitch 1040B
    for (int i = tid; i < 4096; i += 256) {
        int ch = i >> 6, seg = i & 63;
        *(uint4*)(sm + ch * G1_WPITCH + seg * 16) = *(const uint4*)(g_wqk_bf + ch * DD + seg * 8);
    }
    __syncthreads();

    const int mrow = (warp & 3) * 32;  // row slice within 128-row tile
    const int chb  = (warp >> 2) * 32; // ch slice: warps 0-3 -> q, 4-7 -> k
    const uint32_t b_lane = s2u(sm) + (uint32_t)(chb + (lane & 7) + ((lane >> 4) << 3)) * G1_WPITCH
                          + (uint32_t)(((lane >> 3) & 1) << 4);

    const int ntiles = (n + 127) >> 7;
    for (int tile = blockIdx.x; tile < ntiles; tile += (int)gridDim.x) {
        const int row0 = tile << 7;
        float acc[2][4][4];
        #pragma unroll
        for (int m = 0; m < 2; m++)
            #pragma unroll
            for (int nt = 0; nt < 4; nt++)
                #pragma unroll
                for (int j = 0; j < 4; j++) acc[m][nt][j] = 0.f;

        // prologue: chunk 0 LDG + STS
        float4 v[4][2];
        #pragma unroll
        for (int u = 0; u < 4; u++) {
            int idx = tid + (u << 8);
            int row = idx >> 3, seg = idx & 7;
            int gr = row0 + row; if (gr >= n) gr = n - 1;
            const float4* src = (const float4*)(x + (size_t)gr * DD + seg * 8);
            v[u][0] = __ldg(src); v[u][1] = __ldg(src + 1);
        }
        #pragma unroll
        for (int u = 0; u < 4; u++) {
            int idx = tid + (u << 8);
            int row = idx >> 3, seg = idx & 7;
            uint4 pk;
            pk.x = bf2u(v[u][0].x, v[u][0].y); pk.y = bf2u(v[u][0].z, v[u][0].w);
            pk.z = bf2u(v[u][1].x, v[u][1].y); pk.w = bf2u(v[u][1].z, v[u][1].w);
            *(uint4*)(sm + G1_A0 + row * G1_APITCH + seg * 16) = pk;
        }
        __syncthreads();

        #pragma unroll 1
        for (int c = 0; c < 8; c++) {
            const char* abuf = sm + ((c & 1) ? G1_A1 : G1_A0);
            char*       nbuf = sm + ((c & 1) ? G1_A0 : G1_A1);

            if (c < 7) {  // prefetch next chunk into registers
                #pragma unroll
                for (int u = 0; u < 4; u++) {
                    int idx = tid + (u << 8);
                    int row = idx >> 3, seg = idx & 7;
                    int gr = row0 + row; if (gr >= n) gr = n - 1;
                    const float4* src = (const float4*)(x + (size_t)gr * DD + (c + 1) * 64 + seg * 8);
                    v[u][0] = __ldg(src); v[u][1] = __ldg(src + 1);
                }
            }

            uint32_t a_base = s2u(abuf) + (uint32_t)(mrow + (lane & 15)) * G1_APITCH
                            + (uint32_t)(((lane >> 4) & 1) << 4);
            uint32_t w_base = b_lane + (uint32_t)(c * 128);
            #pragma unroll
            for (int ks = 0; ks < 4; ks++) {
                uint32_t a0[4], a1[4], b0[4], b1[4];
                ldsm4(a0, a_base + ks * 32);
                ldsm4(a1, a_base + 16 * G1_APITCH + ks * 32);
                ldsm4(b0, w_base + ks * 32);
                ldsm4(b1, w_base + 16 * G1_WPITCH + ks * 32);
                mma16816(acc[0][0], a0, b0[0], b0[1]);
                mma16816(acc[0][1], a0, b0[2], b0[3]);
                mma16816(acc[0][2], a0, b1[0], b1[1]);
                mma16816(acc[0][3], a0, b1[2], b1[3]);
                mma16816(acc[1][0], a1, b0[0], b0[1]);
                mma16816(acc[1][1], a1, b0[2], b0[3]);
                mma16816(acc[1][2], a1, b1[0], b1[1]);
                mma16816(acc[1][3], a1, b1[2], b1[3]);
            }

            if (c < 7) {  // stage next chunk
                #pragma unroll
                for (int u = 0; u < 4; u++) {
                    int idx = tid + (u << 8);
                    int row = idx >> 3, seg = idx & 7;
                    uint4 pk;
                    pk.x = bf2u(v[u][0].x, v[u][0].y); pk.y = bf2u(v[u][0].z, v[u][0].w);
                    pk.z = bf2u(v[u][1].x, v[u][1].y); pk.w = bf2u(v[u][1].z, v[u][1].w);
                    *(uint4*)(nbuf + row * G1_APITCH + seg * 16) = pk;
                }
            }
            __syncthreads();
        }

        // epilogue: warps 0-3 -> q f32, warps 4-7 -> k bf16
        #pragma unroll
        for (int m = 0; m < 2; m++) {
            int r0 = row0 + mrow + m * 16 + (lane >> 2);
            #pragma unroll
            for (int nt = 0; nt < 4; nt++) {
                int ch = nt * 8 + (lane & 3) * 2;
                if (warp < 4) {
                    if (r0 < n)
                        *(float2*)(g_qemb + (size_t)r0 * HH + ch) = make_float2(acc[m][nt][0], acc[m][nt][1]);
                    if (r0 + 8 < n)
                        *(float2*)(g_qemb + (size_t)(r0 + 8) * HH + ch) = make_float2(acc[m][nt][2], acc[m][nt][3]);
                } else {
                    if (r0 < n)
                        *(uint32_t*)(g_kemb_bf + (size_t)r0 * HH + ch) = bf2u(acc[m][nt][0], acc[m][nt][1]);
                    if (r0 + 8 < n)
                        *(uint32_t*)(g_kemb_bf + (size_t)(r0 + 8) * HH + ch) = bf2u(acc[m][nt][2], acc[m][nt][3]);
                }
            }
        }
    }
}

// ---------------- K2: gather + attention normalize ----------------
// dst = repeat(arange(N), K) => sum_local[n] = q_emb[n] * (sum_j k_emb[src[n*K+j]]) / K
__global__ void __launch_bounds__(256) attn_kernel(const int* __restrict__ src, int n) {
    const int lane = threadIdx.x & 31;
    const int gw   = (blockIdx.x * blockDim.x + threadIdx.x) >> 5;
    const int nw   = (gridDim.x * blockDim.x) >> 5;
    const float ego = g_ego[lane];
    for (int node = gw; node < n; node += nw) {
        int s = src[(size_t)node * 32 + lane];
        float a0 = 0.f, a1 = 0.f, a2 = 0.f, a3 = 0.f;
        #pragma unroll
        for (int j = 0; j < 32; j += 4) {
            int s0 = __shfl_sync(0xffffffffu, s, j);
            int s1 = __shfl_sync(0xffffffffu, s, j + 1);
            int s2 = __shfl_sync(0xffffffffu, s, j + 2);
            int s3 = __shfl_sync(0xffffffffu, s, j + 3);
            a0 += __bfloat162float(g_kemb_bf[(size_t)s0 * HH + lane]);
            a1 += __bfloat162float(g_kemb_bf[(size_t)s1 * HH + lane]);
            a2 += __bfloat162float(g_kemb_bf[(size_t)s2 * HH + lane]);
            a3 += __bfloat162float(g_kemb_bf[(size_t)s3 * HH + lane]);
        }
        float acc = (a0 + a1) + (a2 + a3);
        float q = g_qemb[(size_t)node * HH + lane];
        float sc = ego * q * q + q * acc * (1.f / 32.f);
        float ns = sc;
        #pragma unroll
        for (int o = 16; o; o >>= 1) ns += __shfl_xor_sync(0xffffffffu, ns, o);
        g_attn_bf[(size_t)node * HH + lane] = __float2bfloat16(sc / (ns + 1e-9f));
    }
}

// ---------------- K3: GEMM2  out = attn @ V'  (mma.sync bf16, V frags hoisted) ----------------
// 512 thr, 16 warps. Warp = 16 nodes x 64 d; (warp&1) picks node half, (warp>>1) picks
// one of 8 d-groups of 64 => full D=512 coverage. V frags hoisted (32 regs/warp).
// A = attn tiles [256 nodes][32 h] bf16 via cp.async double-buffer.
#define G2_VPITCH 80
#define G2_A0     40960
#define G2_A1     61440
#define G2_SMEM   81920

__global__ void __launch_bounds__(512, 1) gemm2_kernel(float* __restrict__ out, int n) {
    extern __shared__ __align__(16) char sm[];
    const int tid  = threadIdx.x;
    const int lane = tid & 31;
    const int warp = tid >> 5;

    // one-time: V [512][32] bf16 -> smem pitch 80B
    for (int i = tid; i < 2048; i += 512) {
        int d = i >> 2, seg = i & 3;
        *(uint4*)(sm + d * G2_VPITCH + seg * 16) = *(const uint4*)(g_v_bf + d * HH + seg * 8);
    }
    __syncthreads();

    const int nsl   = (warp & 1) * 16;   // node sub-slice within 32-node subtile
    const int dbase = (warp >> 1) * 64;  // d slice: 8 groups x 64 = 512

    // hoist V fragments: [kstep][ptile][4 regs]; ptile = 16-d group within 64-d slice
    uint32_t bf[2][4][4];
    {
        uint32_t vb = s2u(sm) + (uint32_t)(dbase + (lane & 7) + ((lane >> 4) << 3)) * G2_VPITCH
                    + (uint32_t)(((lane >> 3) & 1) << 4);
        #pragma unroll
        for (int ks = 0; ks < 2; ks++)
            #pragma unroll
            for (int p = 0; p < 4; p++)
                ldsm4(bf[ks][p], vb + (uint32_t)(p * 16 * G2_VPITCH) + (uint32_t)(ks * 32));
    }
    __syncthreads();

    const int ntiles = (n + 255) >> 8;
    int t = blockIdx.x;
    // prologue
    if (t < ntiles) {
        int n0 = t << 8;
        #pragma unroll
        for (int u = 0; u < 2; u++) {
            int idx = tid + (u << 9);
            int row = idx >> 2, seg = idx & 3;
            int node = n0 + row; if (node >= n) node = n - 1;
            cp_async16(sm + G2_A0 + row * G2_VPITCH + seg * 16,
                       g_attn_bf + (size_t)node * HH + seg * 8);
        }
        cp_commit();
    }
    int cur = 0;
    for (; t < ntiles; t += (int)gridDim.x) {
        int tn = t + (int)gridDim.x;
        if (tn < ntiles) {
            int n0 = tn << 8;
            char* dst = sm + (cur ? G2_A0 : G2_A1);
            #pragma unroll
            for (int u = 0; u < 2; u++) {
                int idx = tid + (u << 9);
                int row = idx >> 2, seg = idx & 3;
                int node = n0 + row; if (node >= n) node = n - 1;
                cp_async16(dst + row * G2_VPITCH + seg * 16,
                           g_attn_bf + (size_t)node * HH + seg * 8);
            }
            cp_commit();
            cp_wait<1>();
        } else {
            cp_wait<0>();
        }
        __syncthreads();

        const char* ab = sm + (cur ? G2_A1 : G2_A0);
        const int node0 = t << 8;
        #pragma unroll 1
        for (int sub = 0; sub < 8; sub++) {
            uint32_t a[2][4];
            uint32_t aaddr = s2u(ab) + (uint32_t)((sub * 32 + nsl + (lane & 15)) * G2_VPITCH)
                           + (uint32_t)(((lane >> 4) & 1) << 4);
            ldsm4(a[0], aaddr);
            ldsm4(a[1], aaddr + 32);

            float acc[8][4];
            #pragma unroll
            for (int nt = 0; nt < 8; nt++)
                #pragma unroll
                for (int j = 0; j < 4; j++) acc[nt][j] = 0.f;

            #pragma unroll
            for (int nt = 0; nt < 8; nt++) {
                mma16816(acc[nt], a[0], bf[0][nt >> 1][(nt & 1) * 2], bf[0][nt >> 1][(nt & 1) * 2 + 1]);
                mma16816(acc[nt], a[1], bf[1][nt >> 1][(nt & 1) * 2], bf[1][nt >> 1][(nt & 1) * 2 + 1]);
            }

            int r0 = node0 + sub * 32 + nsl + (lane >> 2);
            #pragma unroll
            for (int nt = 0; nt < 8; nt++) {
                int d = dbase + nt * 8 + (lane & 3) * 2;
                if (r0 < n)
                    *(float2*)(out + (size_t)r0 * DD + d) = make_float2(acc[nt][0], acc[nt][1]);
                if (r0 + 8 < n)
                    *(float2*)(out + (size_t)(r0 + 8) * DD + d) = make_float2(acc[nt][2], acc[nt][3]);
            }
        }
        cur ^= 1;
        __syncthreads();
    }
}

// ---------------- host launcher ----------------
extern "C" void kernel_launch(void* const* d_in, const int* in_sizes, int n_in,
                              void* d_out, int out_size) {
    const int*   adj = (const int*)d_in[0];    // [2, N*K]: row 0 = src
    const float* x   = (const float*)d_in[1];  // [N, 512]
    const float* qw  = (const float*)d_in[2];  // [32, 512]
    const float* kw  = (const float*)d_in[3];  // [32, 512]
    const float* eg  = (const float*)d_in[4];  // [1, 32]
    const float* vw  = (const float*)d_in[5];  // [512, 32]
    float* out = (float*)d_out;

    int n = in_sizes[1] / DD;
    if (n > N_MAX) n = N_MAX;
    if (n <= 0) return;

    int nsm = 148;
    cudaDeviceGetAttribute(&nsm, cudaDevAttrMultiProcessorCount, 0);

    prep_kernel<<<(64 * DD + DD * HH + HH + 255) / 256, 256>>>(qw, kw, eg, vw);

    cudaFuncSetAttribute(gemm1_kernel, cudaFuncAttributeMaxDynamicSharedMemorySize, G1_SMEM);
    gemm1_kernel<<<nsm, 256, G1_SMEM>>>(x, n);

    attn_kernel<<<1024, 256>>>(adj, n);

    cudaFuncSetAttribute(gemm2_kernel, cudaFuncAttributeMaxDynamicSharedMemorySize, G2_SMEM);
    gemm2_kernel<<<nsm, 512, G2_SMEM>>>(out, n);
}

// round 5
// speedup vs baseline: 2.1625x; 1.1243x over previous
#include <cuda_runtime.h>
#include <cuda_bf16.h>
#include <cstdint>

#define N_MAX 100000
#define DD 512
#define HH 32

// ---------------- scratch (static __device__, allocation-free) ----------------
static __device__ __nv_bfloat16 g_v_bf[DD * HH];     // [d][h] = nonneg(v_w[d][h]) bf16
static __device__ float         g_ego[HH];
static __device__ float         g_qemb[N_MAX * HH];  // f32
static __device__ __nv_bfloat16 g_kemb_bf[N_MAX * HH];
static __device__ __nv_bfloat16 g_attn_bf[N_MAX * HH];

// ---------------- helpers ----------------
__device__ __forceinline__ float nonneg(float w) { return w > 0.f ? w + 1.f : __expf(w); }

__device__ __forceinline__ uint32_t s2u(const void* p) {
    return (uint32_t)__cvta_generic_to_shared(p);
}

__device__ __forceinline__ void ldsm4(uint32_t (&r)[4], uint32_t addr) {
    asm volatile("ldmatrix.sync.aligned.m8n8.x4.shared.b16 {%0,%1,%2,%3}, [%4];"
                 : "=r"(r[0]), "=r"(r[1]), "=r"(r[2]), "=r"(r[3]) : "r"(addr));
}

__device__ __forceinline__ void mma16816(float (&d)[4], const uint32_t (&a)[4],
                                         uint32_t b0, uint32_t b1) {
    asm volatile(
        "mma.sync.aligned.m16n8k16.row.col.f32.bf16.bf16.f32 "
        "{%0,%1,%2,%3}, {%4,%5,%6,%7}, {%8,%9}, {%0,%1,%2,%3};"
        : "+f"(d[0]), "+f"(d[1]), "+f"(d[2]), "+f"(d[3])
        : "r"(a[0]), "r"(a[1]), "r"(a[2]), "r"(a[3]), "r"(b0), "r"(b1));
}

__device__ __forceinline__ void cp_async16(void* s, const void* g) {
    asm volatile("cp.async.cg.shared.global [%0], [%1], 16;"
                 :: "r"(s2u(s)), "l"(g));
}
__device__ __forceinline__ void cp_commit() { asm volatile("cp.async.commit_group;"); }
template <int NN>
__device__ __forceinline__ void cp_wait() { asm volatile("cp.async.wait_group %0;" :: "n"(NN)); }

__device__ __forceinline__ uint32_t bf2u(float a, float b) {
    __nv_bfloat162 p = __floats2bfloat162_rn(a, b);
    return *(uint32_t*)&p;
}

// ---------------- K0: V / ego preprocessing ----------------
__global__ void prep_kernel(const float* __restrict__ eg, const float* __restrict__ vw) {
    int i = blockIdx.x * blockDim.x + threadIdx.x;
    if (i < DD * HH) g_v_bf[i] = __float2bfloat16(nonneg(vw[i]));
    int e = i - DD * HH;
    if (e >= 0 && e < HH) g_ego[e] = nonneg(eg[e]);
}

// ---------------- K1: GEMM1  qk_emb = x @ Wqk^T  (mma.sync bf16, XOR swizzle) ----------------
// 2 CTAs/SM (96KB smem each). W [64ch x 512k bf16] 64KB, rows 1024B, XOR swizzle.
// x double-buffered [128 rows x 64k bf16] 16KB each, rows 128B, XOR swizzle.
// Warp tile: 32 rows x 32 ch; warps 0-3 -> q channels, 4-7 -> k channels.
#define G1_A0   65536
#define G1_A1   81920
#define G1_SMEM 98304

__global__ void __launch_bounds__(256, 2) gemm1_kernel(const float* __restrict__ x,
                                                       const float* __restrict__ qw,
                                                       const float* __restrict__ kw, int n) {
    extern __shared__ __align__(16) char sm[];
    const int tid  = threadIdx.x;
    const int lane = tid & 31;
    const int warp = tid >> 5;

    // one-time: W = nonneg(qw/kw)/512 -> bf16 smem, row ch = 1024B, XOR swizzle
    for (int u = tid; u < 4096; u += 256) {
        int ch = u >> 6, seg = u & 63;
        const float* src = (ch < 32) ? (qw + ch * DD) : (kw + (ch - 32) * DD);
        float4 f0 = __ldg((const float4*)(src + seg * 8));
        float4 f1 = __ldg((const float4*)(src + seg * 8) + 1);
        const float sc = 1.f / (float)DD;
        uint4 pk;
        pk.x = bf2u(nonneg(f0.x) * sc, nonneg(f0.y) * sc);
        pk.y = bf2u(nonneg(f0.z) * sc, nonneg(f0.w) * sc);
        pk.z = bf2u(nonneg(f1.x) * sc, nonneg(f1.y) * sc);
        pk.w = bf2u(nonneg(f1.z) * sc, nonneg(f1.w) * sc);
        *(uint4*)(sm + ch * 1024 + ((seg * 16) ^ ((ch & 7) << 4))) = pk;
    }
    __syncthreads();

    const int mrow = (warp & 3) * 32;  // row slice within 128-row tile
    const int chb  = (warp >> 2) * 32; // ch slice: warps 0-3 -> q, 4-7 -> k
    const uint32_t swz  = (uint32_t)((lane & 7) << 4);
    const uint32_t wrow = s2u(sm) + (uint32_t)(chb + (lane & 7) + ((lane >> 4) << 3)) * 1024u;
    const uint32_t whi  = (uint32_t)(((lane >> 3) & 1) << 4);
    const uint32_t ahi  = (uint32_t)(((lane >> 4) & 1) << 4);

    const int ntiles = (n + 127) >> 7;
    for (int tile = blockIdx.x; tile < ntiles; tile += (int)gridDim.x) {
        const int row0 = tile << 7;
        float acc[2][4][4];
        #pragma unroll
        for (int m = 0; m < 2; m++)
            #pragma unroll
            for (int nt = 0; nt < 4; nt++)
                #pragma unroll
                for (int j = 0; j < 4; j++) acc[m][nt][j] = 0.f;

        // prologue: chunk 0 LDG + STS
        float4 v[4][2];
        #pragma unroll
        for (int u = 0; u < 4; u++) {
            int idx = tid + (u << 8);
            int row = idx >> 3, seg = idx & 7;
            int gr = row0 + row; if (gr >= n) gr = n - 1;
            const float4* src = (const float4*)(x + (size_t)gr * DD + seg * 8);
            v[u][0] = __ldg(src); v[u][1] = __ldg(src + 1);
        }
        #pragma unroll
        for (int u = 0; u < 4; u++) {
            int idx = tid + (u << 8);
            int row = idx >> 3, seg = idx & 7;
            uint4 pk;
            pk.x = bf2u(v[u][0].x, v[u][0].y); pk.y = bf2u(v[u][0].z, v[u][0].w);
            pk.z = bf2u(v[u][1].x, v[u][1].y); pk.w = bf2u(v[u][1].z, v[u][1].w);
            *(uint4*)(sm + G1_A0 + row * 128 + ((seg * 16) ^ ((row & 7) << 4))) = pk;
        }
        __syncthreads();

        #pragma unroll 1
        for (int c = 0; c < 8; c++) {
            const uint32_t abase = s2u(sm) + (uint32_t)((c & 1) ? G1_A1 : G1_A0);
            char*          nbuf  = sm + ((c & 1) ? G1_A0 : G1_A1);

            if (c < 7) {  // prefetch next chunk into registers
                #pragma unroll
                for (int u = 0; u < 4; u++) {
                    int idx = tid + (u << 8);
                    int row = idx >> 3, seg = idx & 7;
                    int gr = row0 + row; if (gr >= n) gr = n - 1;
                    const float4* src = (const float4*)(x + (size_t)gr * DD + (c + 1) * 64 + seg * 8);
                    v[u][0] = __ldg(src); v[u][1] = __ldg(src + 1);
                }
            }

            const uint32_t arow0 = abase + (uint32_t)(mrow + (lane & 15)) * 128u;
            #pragma unroll
            for (int ks = 0; ks < 4; ks++) {
                uint32_t a0[4], a1[4], b0[4], b1[4];
                uint32_t akb = ((uint32_t)(ks * 32) + ahi) ^ swz;
                uint32_t wkb = (uint32_t)(c * 128) + (((uint32_t)(ks * 32) + whi) ^ swz);
                ldsm4(a0, arow0 + akb);
                ldsm4(a1, arow0 + 16u * 128u + akb);
                ldsm4(b0, wrow + wkb);
                ldsm4(b1, wrow + 16u * 1024u + wkb);
                mma16816(acc[0][0], a0, b0[0], b0[1]);
                mma16816(acc[0][1], a0, b0[2], b0[3]);
                mma16816(acc[0][2], a0, b1[0], b1[1]);
                mma16816(acc[0][3], a0, b1[2], b1[3]);
                mma16816(acc[1][0], a1, b0[0], b0[1]);
                mma16816(acc[1][1], a1, b0[2], b0[3]);
                mma16816(acc[1][2], a1, b1[0], b1[1]);
                mma16816(acc[1][3], a1, b1[2], b1[3]);
            }

            if (c < 7) {  // stage next chunk
                #pragma unroll
                for (int u = 0; u < 4; u++) {
                    int idx = tid + (u << 8);
                    int row = idx >> 3, seg = idx & 7;
                    uint4 pk;
                    pk.x = bf2u(v[u][0].x, v[u][0].y); pk.y = bf2u(v[u][0].z, v[u][0].w);
                    pk.z = bf2u(v[u][1].x, v[u][1].y); pk.w = bf2u(v[u][1].z, v[u][1].w);
                    *(uint4*)(nbuf + row * 128 + ((seg * 16) ^ ((row & 7) << 4))) = pk;
                }
            }
            __syncthreads();
        }

        // epilogue: warps 0-3 -> q f32, warps 4-7 -> k bf16
        #pragma unroll
        for (int m = 0; m < 2; m++) {
            int r0 = row0 + mrow + m * 16 + (lane >> 2);
            #pragma unroll
            for (int nt = 0; nt < 4; nt++) {
                int ch = nt * 8 + (lane & 3) * 2;
                if (warp < 4) {
                    if (r0 < n)
                        *(float2*)(g_qemb + (size_t)r0 * HH + ch) = make_float2(acc[m][nt][0], acc[m][nt][1]);
                    if (r0 + 8 < n)
                        *(float2*)(g_qemb + (size_t)(r0 + 8) * HH + ch) = make_float2(acc[m][nt][2], acc[m][nt][3]);
                } else {
                    if (r0 < n)
                        *(uint32_t*)(g_kemb_bf + (size_t)r0 * HH + ch) = bf2u(acc[m][nt][0], acc[m][nt][1]);
                    if (r0 + 8 < n)
                        *(uint32_t*)(g_kemb_bf + (size_t)(r0 + 8) * HH + ch) = bf2u(acc[m][nt][2], acc[m][nt][3]);
                }
            }
        }
    }
}

// ---------------- K2: gather + attention normalize (wide gathers) ----------------
// sum_local[n] = q_emb[n] * (sum_j k_emb[src[n*K+j]]) / K.
// Warp per node. lane = (jg = lane>>3, hp = lane&7). Gather = uint2 (4 heads, 8B) per lane:
// 4 neighbor rows per warp-load, 8 loads/node. Reduce jg partials via shfl_xor(8,16).
__global__ void __launch_bounds__(256) attn_kernel(const int* __restrict__ src, int n) {
    const int lane = threadIdx.x & 31;
    const int jg   = lane >> 3;
    const int hp   = lane & 7;
    const int gw   = (blockIdx.x * blockDim.x + threadIdx.x) >> 5;
    const int nw   = (gridDim.x * blockDim.x) >> 5;
    const float4 ego = *(const float4*)(g_ego + hp * 4);

    for (int node = gw; node < n; node += nw) {
        int s = src[(size_t)node * 32 + lane];
        float a0 = 0.f, a1 = 0.f, a2 = 0.f, a3 = 0.f;
        #pragma unroll
        for (int i = 0; i < 8; i++) {
            int sj = __shfl_sync(0xffffffffu, s, i * 4 + jg);
            uint2 kv = __ldg((const uint2*)(g_kemb_bf + (size_t)sj * HH + hp * 4));
            float2 f0 = __bfloat1622float2(*(__nv_bfloat162*)&kv.x);
            float2 f1 = __bfloat1622float2(*(__nv_bfloat162*)&kv.y);
            a0 += f0.x; a1 += f0.y; a2 += f1.x; a3 += f1.y;
        }
        // reduce partials across the 4 jg groups
        a0 += __shfl_xor_sync(0xffffffffu, a0, 8);  a0 += __shfl_xor_sync(0xffffffffu, a0, 16);
        a1 += __shfl_xor_sync(0xffffffffu, a1, 8);  a1 += __shfl_xor_sync(0xffffffffu, a1, 16);
        a2 += __shfl_xor_sync(0xffffffffu, a2, 8);  a2 += __shfl_xor_sync(0xffffffffu, a2, 16);
        a3 += __shfl_xor_sync(0xffffffffu, a3, 8);  a3 += __shfl_xor_sync(0xffffffffu, a3, 16);

        float4 q = *(const float4*)(g_qemb + (size_t)node * HH + hp * 4);
        const float k1 = 1.f / 32.f;
        float s0 = ego.x * q.x * q.x + q.x * a0 * k1;
        float s1 = ego.y * q.y * q.y + q.y * a1 * k1;
        float s2 = ego.z * q.z * q.z + q.z * a2 * k1;
        float s3 = ego.w * q.w * q.w + q.w * a3 * k1;

        float ns = (s0 + s1) + (s2 + s3);
        ns += __shfl_xor_sync(0xffffffffu, ns, 1);
        ns += __shfl_xor_sync(0xffffffffu, ns, 2);
        ns += __shfl_xor_sync(0xffffffffu, ns, 4);
        float inv = 1.f / (ns + 1e-9f);

        if (jg == 0) {
            uint2 pk;
            pk.x = bf2u(s0 * inv, s1 * inv);
            pk.y = bf2u(s2 * inv, s3 * inv);
            *(uint2*)(g_attn_bf + (size_t)node * HH + hp * 4) = pk;
        }
    }
}

// ---------------- K3: GEMM2  out = attn @ V'  (mma.sync bf16, V frags hoisted) ----------------
// 512 thr, 16 warps. Warp = 16 nodes x 64 d; full D=512 coverage. V frags in registers.
// A = attn tiles [256 nodes][32 h] bf16 via cp.async double-buffer.
#define G2_VPITCH 80
#define G2_A0     40960
#define G2_A1     61440
#define G2_SMEM   81920

__global__ void __launch_bounds__(512, 1) gemm2_kernel(float* __restrict__ out, int n) {
    extern __shared__ __align__(16) char sm[];
    const int tid  = threadIdx.x;
    const int lane = tid & 31;
    const int warp = tid >> 5;

    // one-time: V [512][32] bf16 -> smem pitch 80B
    for (int i = tid; i < 2048; i += 512) {
        int d = i >> 2, seg = i & 3;
        *(uint4*)(sm + d * G2_VPITCH + seg * 16) = *(const uint4*)(g_v_bf + d * HH + seg * 8);
    }
    __syncthreads();

    const int nsl   = (warp & 1) * 16;   // node sub-slice within 32-node subtile
    const int dbase = (warp >> 1) * 64;  // d slice: 8 groups x 64 = 512

    // hoist V fragments: [kstep][ptile][4 regs]
    uint32_t bf[2][4][4];
    {
        uint32_t vb = s2u(sm) + (uint32_t)(dbase + (lane & 7) + ((lane >> 4) << 3)) * G2_VPITCH
                    + (uint32_t)(((lane >> 3) & 1) << 4);
        #pragma unroll
        for (int ks = 0; ks < 2; ks++)
            #pragma unroll
            for (int p = 0; p < 4; p++)
                ldsm4(bf[ks][p], vb + (uint32_t)(p * 16 * G2_VPITCH) + (uint32_t)(ks * 32));
    }
    __syncthreads();

    const int ntiles = (n + 255) >> 8;
    int t = blockIdx.x;
    if (t < ntiles) {
        int n0 = t << 8;
        #pragma unroll
        for (int u = 0; u < 2; u++) {
            int idx = tid + (u << 9);
            int row = idx >> 2, seg = idx & 3;
            int node = n0 + row; if (node >= n) node = n - 1;
            cp_async16(sm + G2_A0 + row * G2_VPITCH + seg * 16,
                       g_attn_bf + (size_t)node * HH + seg * 8);
        }
        cp_commit();
    }
    int cur = 0;
    for (; t < ntiles; t += (int)gridDim.x) {
        int tn = t + (int)gridDim.x;
        if (tn < ntiles) {
            int n0 = tn << 8;
            char* dst = sm + (cur ? G2_A0 : G2_A1);
            #pragma unroll
            for (int u = 0; u < 2; u++) {
                int idx = tid + (u << 9);
                int row = idx >> 2, seg = idx & 3;
                int node = n0 + row; if (node >= n) node = n - 1;
                cp_async16(dst + row * G2_VPITCH + seg * 16,
                           g_attn_bf + (size_t)node * HH + seg * 8);
            }
            cp_commit();
            cp_wait<1>();
        } else {
            cp_wait<0>();
        }
        __syncthreads();

        const char* ab = sm + (cur ? G2_A1 : G2_A0);
        const int node0 = t << 8;
        #pragma unroll 1
        for (int sub = 0; sub < 8; sub++) {
            uint32_t a[2][4];
            uint32_t aaddr = s2u(ab) + (uint32_t)((sub * 32 + nsl + (lane & 15)) * G2_VPITCH)
                           + (uint32_t)(((lane >> 4) & 1) << 4);
            ldsm4(a[0], aaddr);
            ldsm4(a[1], aaddr + 32);

            float acc[8][4];
            #pragma unroll
            for (int nt = 0; nt < 8; nt++)
                #pragma unroll
                for (int j = 0; j < 4; j++) acc[nt][j] = 0.f;

            #pragma unroll
            for (int nt = 0; nt < 8; nt++) {
                mma16816(acc[nt], a[0], bf[0][nt >> 1][(nt & 1) * 2], bf[0][nt >> 1][(nt & 1) * 2 + 1]);
                mma16816(acc[nt], a[1], bf[1][nt >> 1][(nt & 1) * 2], bf[1][nt >> 1][(nt & 1) * 2 + 1]);
            }

            int r0 = node0 + sub * 32 + nsl + (lane >> 2);
            #pragma unroll
            for (int nt = 0; nt < 8; nt++) {
                int d = dbase + nt * 8 + (lane & 3) * 2;
                if (r0 < n)
                    *(float2*)(out + (size_t)r0 * DD + d) = make_float2(acc[nt][0], acc[nt][1]);
                if (r0 + 8 < n)
                    *(float2*)(out + (size_t)(r0 + 8) * DD + d) = make_float2(acc[nt][2], acc[nt][3]);
            }
        }
        cur ^= 1;
        __syncthreads();
    }
}

// ---------------- host launcher ----------------
extern "C" void kernel_launch(void* const* d_in, const int* in_sizes, int n_in,
                              void* d_out, int out_size) {
    const int*   adj = (const int*)d_in[0];    // [2, N*K]: row 0 = src
    const float* x   = (const float*)d_in[1];  // [N, 512]
    const float* qw  = (const float*)d_in[2];  // [32, 512]
    const float* kw  = (const float*)d_in[3];  // [32, 512]
    const float* eg  = (const float*)d_in[4];  // [1, 32]
    const float* vw  = (const float*)d_in[5];  // [512, 32]
    float* out = (float*)d_out;

    int n = in_sizes[1] / DD;
    if (n > N_MAX) n = N_MAX;
    if (n <= 0) return;

    int nsm = 148;
    cudaDeviceGetAttribute(&nsm, cudaDevAttrMultiProcessorCount, 0);

    prep_kernel<<<(DD * HH + HH + 255) / 256, 256>>>(eg, vw);

    cudaFuncSetAttribute(gemm1_kernel, cudaFuncAttributeMaxDynamicSharedMemorySize, G1_SMEM);
    gemm1_kernel<<<2 * nsm, 256, G1_SMEM>>>(x, qw, kw, n);

    attn_kernel<<<1024, 256>>>(adj, n);

    cudaFuncSetAttribute(gemm2_kernel, cudaFuncAttributeMaxDynamicSharedMemorySize, G2_SMEM);
    gemm2_kernel<<<nsm, 512, G2_SMEM>>>(out, n);
}